// round 6
// baseline (speedup 1.0000x reference)
#include <cuda_runtime.h>
#include <cuda_bf16.h>

// Problem constants
#define NPTS   16384
#define B_BAT  8
#define NPOINT 1024
#define NSAMP  32
#define DIN    64
#define CIN0   67        // 3 + 64
#define H1DIM  64
#define H2DIM  128
#define H3DIM  256

// Scratch (device globals; no runtime allocation)
__device__ int   g_fps[B_BAT * NPOINT];
__device__ int   g_nb[B_BAT * NPOINT * NSAMP];
__device__ float g_Wt[4288 + 8192 + 32768];   // W0t(67x64) | W1t(64x128) | W2t(128x256)

// exact (non-contracted) squared distance, XLA reduce order ((dx^2+dy^2)+dz^2)
__device__ __forceinline__ float sqdist(float dx, float dy, float dz) {
    return __fadd_rn(__fadd_rn(__fmul_rn(dx, dx), __fmul_rn(dy, dy)), __fmul_rn(dz, dz));
}

__device__ __forceinline__ float silu_f(float x) {
    return x / (1.0f + __expf(-x));
}

// ---------------------------------------------------------------------------
// Kernel 1: farthest point sampling. One CTA per batch, 1024 threads,
// 16 points/thread (p = tid + i*1024). x,y in smem; z and dist in registers.
// ---------------------------------------------------------------------------
__global__ void __launch_bounds__(1024, 1)
fps_kernel(const float* __restrict__ xyz) {
    extern __shared__ float smf[];
    float* sx = smf;              // [16384]
    float* sy = smf + NPTS;       // [16384]
    float* sz = smf + 2 * NPTS;   // [16384] (read only for centroid lookup)

    __shared__ float s_wv[32];
    __shared__ int   s_wi[32];
    __shared__ int   s_cur;

    const int b = blockIdx.x;
    const int t = threadIdx.x;
    const float* base = xyz + (size_t)b * 3 * NPTS;

    float zr[16];
    float dist[16];
#pragma unroll
    for (int i = 0; i < 16; i++) {
        int p = t + i * 1024;
        sx[p] = base[p];
        sy[p] = base[NPTS + p];
        float z = base[2 * NPTS + p];
        sz[p] = z;
        zr[i] = z;
        dist[i] = __int_as_float(0x7f800000);  // +inf
    }
    int cur = 0;
    __syncthreads();

    for (int s = 0; s < NPOINT; s++) {
        if (t == 0) g_fps[b * NPOINT + s] = cur;   // scan emits OLD farthest
        float cx = sx[cur], cy = sy[cur], cz = sz[cur];

        float bv = -1.0f;
        int   bi = 0;
#pragma unroll
        for (int i = 0; i < 16; i++) {
            int p = t + i * 1024;
            float dx = sx[p] - cx;
            float dy = sy[p] - cy;
            float dz = zr[i] - cz;
            float d  = sqdist(dx, dy, dz);
            float nd = fminf(dist[i], d);
            dist[i] = nd;
            if (nd > bv) { bv = nd; bi = p; }      // ascending p: first-occurrence
        }
        // warp argmax reduce, tie -> lower index
#pragma unroll
        for (int off = 16; off; off >>= 1) {
            float ov = __shfl_down_sync(0xffffffffu, bv, off);
            int   oi = __shfl_down_sync(0xffffffffu, bi, off);
            if (ov > bv || (ov == bv && oi < bi)) { bv = ov; bi = oi; }
        }
        int w = t >> 5;
        if ((t & 31) == 0) { s_wv[w] = bv; s_wi[w] = bi; }
        __syncthreads();
        if (w == 0) {
            bv = s_wv[t & 31];
            bi = s_wi[t & 31];
#pragma unroll
            for (int off = 16; off; off >>= 1) {
                float ov = __shfl_down_sync(0xffffffffu, bv, off);
                int   oi = __shfl_down_sync(0xffffffffu, bi, off);
                if (ov > bv || (ov == bv && oi < bi)) { bv = ov; bi = oi; }
            }
            if (t == 0) s_cur = bi;
        }
        __syncthreads();
        cur = s_cur;
    }
}

// ---------------------------------------------------------------------------
// Kernel 2: ball query. One warp per (b,s) query; ordered ballot scan,
// early exit once 32 in-radius indices found; pad with first index.
// ---------------------------------------------------------------------------
__global__ void bq_kernel(const float* __restrict__ xyz) {
    const int warp = (blockIdx.x * blockDim.x + threadIdx.x) >> 5;
    const int lane = threadIdx.x & 31;
    if (warp >= B_BAT * NPOINT) return;
    const int b = warp >> 10;

    const float* px = xyz + (size_t)b * 3 * NPTS;
    const int qi = g_fps[warp];
    const float qx = px[qi], qy = px[NPTS + qi], qz = px[2 * NPTS + qi];

    int cnt = 0;
    int first = 0;
    for (int ch = 0; ch < NPTS / 32; ch++) {
        if (cnt >= NSAMP) break;
        int p = ch * 32 + lane;
        float dx = px[p] - qx;
        float dy = px[NPTS + p] - qy;
        float dz = px[2 * NPTS + p] - qz;
        float d  = sqdist(dx, dy, dz);
        bool ok = !(d > 0.04f);                    // keep iff sqr <= r^2
        unsigned mask = __ballot_sync(0xffffffffu, ok);
        if (cnt == 0 && mask) first = ch * 32 + (__ffs(mask) - 1);
        int rank = cnt + __popc(mask & ((1u << lane) - 1u));
        if (ok && rank < NSAMP) g_nb[warp * NSAMP + rank] = p;
        cnt += __popc(mask);
    }
    if (cnt < NSAMP) {
        for (int r = cnt + lane; r < NSAMP; r += 32)
            g_nb[warp * NSAMP + r] = first;
    }
}

// ---------------------------------------------------------------------------
// Kernel 3: transpose weights into g_Wt as Wt[c][o] (o contiguous).
// ---------------------------------------------------------------------------
__global__ void prep_kernel(const float* __restrict__ w0,
                            const float* __restrict__ w1,
                            const float* __restrict__ w2) {
    int i = blockIdx.x * 256 + threadIdx.x;
    if (i < 4288) {                               // W0t: 67 x 64
        int c = i >> 6, o = i & 63;
        g_Wt[i] = w0[o * CIN0 + c];
    } else if (i < 4288 + 8192) {                 // W1t: 64 x 128
        int j = i - 4288;
        int c = j >> 7, o = j & 127;
        g_Wt[i] = w1[o * H1DIM + c];
    } else if (i < 4288 + 8192 + 32768) {         // W2t: 128 x 256
        int j = i - (4288 + 8192);
        int c = j >> 8, o = j & 255;
        g_Wt[i] = w2[o * H2DIM + c];
    }
}

// ---------------------------------------------------------------------------
// Kernel 4: fused gather + 3-layer MLP + mean. 256 threads/CTA, 8 groups/CTA.
// All weights in smem (transposed), register-tiled fp32 FMA.
// smem layout (floats):
//   W0t 0..4288 | W1t 4288..12480 | W2t 12480..45248 |
//   b0 45248 | b1 45312 | b2 45440 |
//   X0 45696 (32x68) | H1 47872 (32x64) | H2 49920 (32x128) |
//   Red 54016 (8x256) | nbr 56064 (32 int) | q 56096 (3) -> 56100 floats
// ---------------------------------------------------------------------------
#define SM_W0   0
#define SM_W1   4288
#define SM_W2   12480
#define SM_B0   45248
#define SM_B1   45312
#define SM_B2   45440
#define SM_X0   45696
#define SM_H1   47872
#define SM_H2   49920
#define SM_RED  54016
#define SM_NBR  56064
#define SM_Q    56096
#define MLP_SMEM_FLOATS 56100

__global__ void __launch_bounds__(256, 1)
mlp_kernel(const float* __restrict__ xyz, const float* __restrict__ pts,
           const float* __restrict__ b0, const float* __restrict__ b1,
           const float* __restrict__ b2, float* __restrict__ out) {
    extern __shared__ float smf[];
    float* W0t = smf + SM_W0;
    float* W1t = smf + SM_W1;
    float* W2t = smf + SM_W2;
    float* b0s = smf + SM_B0;
    float* b1s = smf + SM_B1;
    float* b2s = smf + SM_B2;
    float* X0  = smf + SM_X0;
    float* H1  = smf + SM_H1;
    float* H2  = smf + SM_H2;
    float* Red = smf + SM_RED;
    int*   nbr = (int*)(smf + SM_NBR);
    float* qp  = smf + SM_Q;

    const int t = threadIdx.x;

    // stage weights (coalesced float4) + biases
    {
        const float4* src = (const float4*)g_Wt;
        float4* dst = (float4*)smf;
        for (int i = t; i < 45248 / 4; i += 256) dst[i] = src[i];
        if (t < 64)  b0s[t] = b0[t];
        if (t < 128) b1s[t] = b1[t];
        b2s[t] = b2[t];
    }
    __syncthreads();

    for (int gi = 0; gi < 8; gi++) {
        const int g = blockIdx.x * 8 + gi;
        const int b = g >> 10;
        const int s = g & 1023;
        const float* px = xyz + (size_t)b * 3 * NPTS;
        const float* pp = pts + (size_t)b * DIN * NPTS;

        if (t < NSAMP) nbr[t] = g_nb[g * NSAMP + t];
        if (t == NSAMP) {
            int qi = g_fps[g];
            qp[0] = px[qi]; qp[1] = px[NPTS + qi]; qp[2] = px[2 * NPTS + qi];
        }
        __syncthreads();

        // gather X0[k][c], c<3: xyz - q ; else point feature
        for (int j = t; j < NSAMP * CIN0; j += 256) {
            int k = j / CIN0;
            int c = j - k * CIN0;
            int nk = nbr[k];
            float v = (c < 3) ? (px[c * NPTS + nk] - qp[c])
                              : pp[(c - 3) * NPTS + nk];
            X0[k * 68 + c] = v;
        }
        __syncthreads();

        // ---- Layer 0: 67 -> 64, tile 2k x 4o ----
        {
            const int ot = t & 15, kt = t >> 4;
            const int o0 = ot * 4, k0 = kt * 2;
            float a0x = 0, a0y = 0, a0z = 0, a0w = 0;
            float a1x = 0, a1y = 0, a1z = 0, a1w = 0;
            const float* xr0 = &X0[k0 * 68];
            const float* xr1 = xr0 + 68;
#pragma unroll 4
            for (int c = 0; c < CIN0; c++) {
                float4 w = *(const float4*)&W0t[c * 64 + o0];
                float x0 = xr0[c], x1 = xr1[c];
                a0x += x0 * w.x; a0y += x0 * w.y; a0z += x0 * w.z; a0w += x0 * w.w;
                a1x += x1 * w.x; a1y += x1 * w.y; a1z += x1 * w.z; a1w += x1 * w.w;
            }
            float4 bb = *(const float4*)&b0s[o0];
            float4 h0 = make_float4(silu_f(a0x + bb.x), silu_f(a0y + bb.y),
                                    silu_f(a0z + bb.z), silu_f(a0w + bb.w));
            float4 h1v = make_float4(silu_f(a1x + bb.x), silu_f(a1y + bb.y),
                                     silu_f(a1z + bb.z), silu_f(a1w + bb.w));
            *(float4*)&H1[k0 * 64 + o0] = h0;
            *(float4*)&H1[(k0 + 1) * 64 + o0] = h1v;
        }
        __syncthreads();

        // ---- Layer 1: 64 -> 128, tile 4k x 4o ----
        {
            const int ot = t & 31, kt = t >> 5;
            const int o0 = ot * 4, k0 = kt * 4;
            float acc[4][4];
#pragma unroll
            for (int kk = 0; kk < 4; kk++)
#pragma unroll
                for (int j = 0; j < 4; j++) acc[kk][j] = 0.0f;
#pragma unroll 4
            for (int c = 0; c < H1DIM; c++) {
                float4 w = *(const float4*)&W1t[c * 128 + o0];
#pragma unroll
                for (int kk = 0; kk < 4; kk++) {
                    float x = H1[(k0 + kk) * 64 + c];
                    acc[kk][0] += x * w.x; acc[kk][1] += x * w.y;
                    acc[kk][2] += x * w.z; acc[kk][3] += x * w.w;
                }
            }
            float4 bb = *(const float4*)&b1s[o0];
#pragma unroll
            for (int kk = 0; kk < 4; kk++) {
                float4 h = make_float4(silu_f(acc[kk][0] + bb.x), silu_f(acc[kk][1] + bb.y),
                                       silu_f(acc[kk][2] + bb.z), silu_f(acc[kk][3] + bb.w));
                *(float4*)&H2[(k0 + kk) * 128 + o0] = h;
            }
        }
        __syncthreads();

        // ---- Layer 2: 128 -> 256, tile 4k x 8o, fused bias+silu+k-sum ----
        {
            const int ot = t & 31, kt = t >> 5;
            const int o0 = ot * 8, k0 = kt * 4;
            float acc[4][8];
#pragma unroll
            for (int kk = 0; kk < 4; kk++)
#pragma unroll
                for (int j = 0; j < 8; j++) acc[kk][j] = 0.0f;
#pragma unroll 4
            for (int c = 0; c < H2DIM; c++) {
                float4 wA = *(const float4*)&W2t[c * 256 + o0];
                float4 wB = *(const float4*)&W2t[c * 256 + o0 + 4];
#pragma unroll
                for (int kk = 0; kk < 4; kk++) {
                    float x = H2[(k0 + kk) * 128 + c];
                    acc[kk][0] += x * wA.x; acc[kk][1] += x * wA.y;
                    acc[kk][2] += x * wA.z; acc[kk][3] += x * wA.w;
                    acc[kk][4] += x * wB.x; acc[kk][5] += x * wB.y;
                    acc[kk][6] += x * wB.z; acc[kk][7] += x * wB.w;
                }
            }
            float part[8];
#pragma unroll
            for (int j = 0; j < 8; j++) {
                float bb = b2s[o0 + j];
                float sum = 0.0f;
#pragma unroll
                for (int kk = 0; kk < 4; kk++) sum += silu_f(acc[kk][j] + bb);
                part[j] = sum;
            }
            *(float4*)&Red[kt * 256 + o0]     = make_float4(part[0], part[1], part[2], part[3]);
            *(float4*)&Red[kt * 256 + o0 + 4] = make_float4(part[4], part[5], part[6], part[7]);
        }
        __syncthreads();

        // ---- k-mean reduce across 8 kt rows; one output channel per thread ----
        {
            float sum = 0.0f;
#pragma unroll
            for (int r = 0; r < 8; r++) sum += Red[r * 256 + t];
            out[(size_t)b * (H3DIM * NPOINT) + (size_t)t * NPOINT + s] = sum * (1.0f / 32.0f);
        }
        __syncthreads();
    }
}

// ---------------------------------------------------------------------------
extern "C" void kernel_launch(void* const* d_in, const int* in_sizes, int n_in,
                              void* d_out, int out_size) {
    const float* xyz = (const float*)d_in[0];
    const float* pts = (const float*)d_in[1];
    const float* w0  = (const float*)d_in[2];
    const float* b0  = (const float*)d_in[3];
    const float* w1  = (const float*)d_in[4];
    const float* b1  = (const float*)d_in[5];
    const float* w2  = (const float*)d_in[6];
    const float* b2  = (const float*)d_in[7];
    float* out = (float*)d_out;

    const int fps_smem = 3 * NPTS * (int)sizeof(float);            // 196608
    const int mlp_smem = MLP_SMEM_FLOATS * (int)sizeof(float);     // 224400

    cudaFuncSetAttribute(fps_kernel, cudaFuncAttributeMaxDynamicSharedMemorySize, fps_smem);
    cudaFuncSetAttribute(mlp_kernel, cudaFuncAttributeMaxDynamicSharedMemorySize, mlp_smem);

    prep_kernel<<<(45248 + 255) / 256, 256>>>(w0, w1, w2);
    fps_kernel<<<B_BAT, 1024, fps_smem>>>(xyz);
    bq_kernel<<<(B_BAT * NPOINT) / 8, 256>>>(xyz);
    mlp_kernel<<<(B_BAT * NPOINT) / 8, 256, mlp_smem>>>(xyz, pts, b0, b1, b2, out);
}

// round 7
// speedup vs baseline: 1.0425x; 1.0425x over previous
#include <cuda_runtime.h>
#include <cuda_bf16.h>

#define NPTS   16384
#define B_BAT  8
#define NPOINT 1024
#define NSAMP  32
#define DIN    64
#define CIN0   67
#define H1DIM  64
#define H2DIM  128
#define H3DIM  256

// Scratch (device globals; no runtime allocation)
__device__ int   g_fps[B_BAT * NPOINT];
__device__ int   g_nb[B_BAT * NPOINT * NSAMP];
__device__ float g_Wt[4288 + 8192 + 32768];   // W0t(67x64) | W1t(64x128) | W2t(128x256)

// exact (non-contracted) squared distance, XLA reduce order ((dx^2+dy^2)+dz^2)
__device__ __forceinline__ float sqdist(float dx, float dy, float dz) {
    return __fadd_rn(__fadd_rn(__fmul_rn(dx, dx), __fmul_rn(dy, dy)), __fmul_rn(dz, dz));
}

__device__ __forceinline__ float silu_f(float x) {
    return __fdividef(x, 1.0f + __expf(-x));
}

// ---- packed fp32x2 helpers (sm_103a FFMA2 path) ----
#define FMA2(acc, x, w) asm("fma.rn.f32x2 %0, %1, %2, %0;" : "+l"(acc) : "l"(x), "l"(w))
#define PACK2(d, s)     asm("mov.b64 %0, {%1, %1};" : "=l"(d) : "f"(s))
#define UNPACK2(lo, hi, v) asm("mov.b64 {%0, %1}, %2;" : "=f"(lo), "=f"(hi) : "l"(v))

// ---------------------------------------------------------------------------
// Kernel 1: farthest point sampling, 8-CTA cluster per batch.
// Each CTA owns 2048 points fully in registers (x,y,z,dist x 8 per thread).
// Per step: local argmax (redux.sync), candidate record (val,idx,x,y,z)
// pushed to all 8 CTAs via DSMEM, cluster barrier, identical resolve.
// ---------------------------------------------------------------------------
__global__ void __launch_bounds__(256, 1) __cluster_dims__(8, 1, 1)
fps_kernel(const float* __restrict__ xyz) {
    __shared__ float slots[2][8][8];   // [buf][src_rank][val, idx_bits, x, y, z, pad...]
    __shared__ float s_wv[8];
    __shared__ int   s_wi[8];

    unsigned rank;
    asm("mov.u32 %0, %%cluster_ctarank;" : "=r"(rank));
    const int b = blockIdx.x >> 3;
    const int t = threadIdx.x;
    const float* px = xyz + (size_t)b * 3 * NPTS;
    const int base = (int)rank * 2048;

    unsigned slot_base;
    asm("{ .reg .u64 tt; cvta.to.shared.u64 tt, %1; cvt.u32.u64 %0, tt; }"
        : "=r"(slot_base) : "l"(&slots[0][0][0]));

    float x[8], y[8], z[8], dist[8];
#pragma unroll
    for (int j = 0; j < 8; j++) {
        int p = base + j * 256 + t;
        x[j] = px[p];
        y[j] = px[NPTS + p];
        z[j] = px[2 * NPTS + p];
        dist[j] = __int_as_float(0x7f800000);
    }
    float cx = px[0], cy = px[NPTS], cz = px[2 * NPTS];
    int cur = 0;

    for (int s = 0; s < NPOINT; s++) {
        if (rank == 0 && t == 0) g_fps[b * NPOINT + s] = cur;

        // local min-update + argmax (ascending j => first-occurrence)
        float bv = -1.0f;
        int   bi = 0;
#pragma unroll
        for (int j = 0; j < 8; j++) {
            float dx = __fsub_rn(x[j], cx);
            float dy = __fsub_rn(y[j], cy);
            float dz = __fsub_rn(z[j], cz);
            float d  = sqdist(dx, dy, dz);
            float nd = fminf(dist[j], d);
            dist[j] = nd;
            if (nd > bv) { bv = nd; bi = base + j * 256 + t; }
        }
        // warp argmax via redux (bv >= 0 so float bits are order-preserving)
        unsigned vb = __float_as_uint(bv);
        unsigned mv = __reduce_max_sync(0xffffffffu, vb);
        unsigned ic = (vb == mv) ? (unsigned)bi : 0xffffffffu;
        unsigned mi = __reduce_min_sync(0xffffffffu, ic);
        if ((t & 31) == 0) { s_wv[t >> 5] = __uint_as_float(mv); s_wi[t >> 5] = (int)mi; }
        __syncthreads();

        // every thread reduces the 8 warp records (broadcast reads)
        float cv = s_wv[0]; int cp = s_wi[0];
#pragma unroll
        for (int r = 1; r < 8; r++) {
            float fv = s_wv[r]; int fi = s_wi[r];
            if (fv > cv || (fv == cv && fi < cp)) { cv = fv; cp = fi; }
        }

        // owner thread publishes (val, idx, coords) to all 8 CTAs
        int local = cp - base;
        if ((local & 255) == t) {
            int j = local >> 8;
            float ox = x[0], oy = y[0], oz = z[0];
#pragma unroll
            for (int jj = 1; jj < 8; jj++)
                if (jj == j) { ox = x[jj]; oy = y[jj]; oz = z[jj]; }
            unsigned la = slot_base + (unsigned)(((s & 1) * 8 + (int)rank) * 8) * 4u;
#pragma unroll
            for (int r = 0; r < 8; r++) {
                unsigned ra;
                asm("mapa.shared::cluster.u32 %0, %1, %2;" : "=r"(ra) : "r"(la), "r"(r));
                asm volatile("st.shared::cluster.f32 [%0], %1;"      :: "r"(ra),        "f"(cv));
                asm volatile("st.shared::cluster.u32 [%0+4], %1;"    :: "r"(ra),        "r"((unsigned)cp));
                asm volatile("st.shared::cluster.f32 [%0+8], %1;"    :: "r"(ra),        "f"(ox));
                asm volatile("st.shared::cluster.f32 [%0+12], %1;"   :: "r"(ra),        "f"(oy));
                asm volatile("st.shared::cluster.f32 [%0+16], %1;"   :: "r"(ra),        "f"(oz));
            }
        }
        asm volatile("barrier.cluster.arrive.aligned;" ::: "memory");
        asm volatile("barrier.cluster.wait.aligned;"   ::: "memory");

        // resolve global winner from the 8 records (identical in every CTA)
        const float* rec = &slots[s & 1][0][0];
        float gv = rec[0];
        int   gp = (int)__float_as_uint(rec[1]);
        float nx = rec[2], ny = rec[3], nz = rec[4];
#pragma unroll
        for (int r = 1; r < 8; r++) {
            const float* rr = rec + r * 8;
            float fv = rr[0];
            int   fi = (int)__float_as_uint(rr[1]);
            if (fv > gv || (fv == gv && fi < gp)) {
                gv = fv; gp = fi; nx = rr[2]; ny = rr[3]; nz = rr[4];
            }
        }
        cur = gp; cx = nx; cy = ny; cz = nz;
    }
}

// ---------------------------------------------------------------------------
// Kernel 2: ball query. One warp per (b,s); ordered ballot scan, early exit.
// ---------------------------------------------------------------------------
__global__ void bq_kernel(const float* __restrict__ xyz) {
    const int warp = (blockIdx.x * blockDim.x + threadIdx.x) >> 5;
    const int lane = threadIdx.x & 31;
    if (warp >= B_BAT * NPOINT) return;
    const int b = warp >> 10;

    const float* px = xyz + (size_t)b * 3 * NPTS;
    const int qi = g_fps[warp];
    const float qx = px[qi], qy = px[NPTS + qi], qz = px[2 * NPTS + qi];

    int cnt = 0;
    int first = 0;
    for (int ch = 0; ch < NPTS / 32; ch++) {
        if (cnt >= NSAMP) break;
        int p = ch * 32 + lane;
        float dx = __fsub_rn(px[p], qx);
        float dy = __fsub_rn(px[NPTS + p], qy);
        float dz = __fsub_rn(px[2 * NPTS + p], qz);
        float d  = sqdist(dx, dy, dz);
        bool ok = !(d > 0.04f);
        unsigned mask = __ballot_sync(0xffffffffu, ok);
        if (cnt == 0 && mask) first = ch * 32 + (__ffs(mask) - 1);
        int rank = cnt + __popc(mask & ((1u << lane) - 1u));
        if (ok && rank < NSAMP) g_nb[warp * NSAMP + rank] = p;
        cnt += __popc(mask);
    }
    if (cnt < NSAMP) {
        for (int r = cnt + lane; r < NSAMP; r += 32)
            g_nb[warp * NSAMP + r] = first;
    }
}

// ---------------------------------------------------------------------------
// Kernel 3: transpose weights into g_Wt as Wt[c][o] (o contiguous).
// ---------------------------------------------------------------------------
__global__ void prep_kernel(const float* __restrict__ w0,
                            const float* __restrict__ w1,
                            const float* __restrict__ w2) {
    int i = blockIdx.x * 256 + threadIdx.x;
    if (i < 4288) {
        int c = i >> 6, o = i & 63;
        g_Wt[i] = w0[o * CIN0 + c];
    } else if (i < 4288 + 8192) {
        int j = i - 4288;
        int c = j >> 7, o = j & 127;
        g_Wt[i] = w1[o * H1DIM + c];
    } else if (i < 4288 + 8192 + 32768) {
        int j = i - (4288 + 8192);
        int c = j >> 8, o = j & 255;
        g_Wt[i] = w2[o * H2DIM + c];
    }
}

// ---------------------------------------------------------------------------
// Kernel 4: fused gather + 3-layer MLP + mean. 512 threads, persistent CTAs,
// packed f32x2 FMAs, all weights in smem.
// smem (floats):
//   W0t 0 | W1t 4288 | W2t 12480 | X0 45248 (32x68) | H1 47424 (32x64) |
//   H2 49472 (32x128) | Red(=X0 alias) 45248 (16x256) | nbr 53568 | q 53600
// ---------------------------------------------------------------------------
#define SM_W0   0
#define SM_W1   4288
#define SM_W2   12480
#define SM_X0   45248
#define SM_H1   47424
#define SM_H2   49472
#define SM_RED  45248
#define SM_NBR  53568
#define SM_Q    53600
#define MLP_SMEM_FLOATS 53604

__global__ void __launch_bounds__(512, 1)
mlp_kernel(const float* __restrict__ xyz, const float* __restrict__ pts,
           const float* __restrict__ b0, const float* __restrict__ b1,
           const float* __restrict__ b2, float* __restrict__ out) {
    extern __shared__ float smf[];
    float* W0t = smf + SM_W0;
    float* W1t = smf + SM_W1;
    float* W2t = smf + SM_W2;
    float* X0  = smf + SM_X0;
    float* H1  = smf + SM_H1;
    float* H2  = smf + SM_H2;
    float* Red = smf + SM_RED;
    int*   nbr = (int*)(smf + SM_NBR);
    float* qp  = smf + SM_Q;

    const int t = threadIdx.x;

    // stage weights once per CTA
    {
        const float4* src = (const float4*)g_Wt;
        float4* dst = (float4*)smf;
        for (int i = t; i < 45248 / 4; i += 512) dst[i] = src[i];
    }

    // per-thread tile coordinates + bias preload (registers)
    const int ot0 = t & 15, kt0 = t >> 4, o0 = ot0 * 4;
    const int ot1 = t & 15, kt1 = t >> 4, o1 = ot1 * 8;
    const int ot2 = t & 31, kt2 = t >> 5, o2 = ot2 * 8, k2 = kt2 * 2;

    float bias0[4], bias1[8], bias2[8];
#pragma unroll
    for (int i = 0; i < 4; i++) bias0[i] = b0[o0 + i];
#pragma unroll
    for (int i = 0; i < 8; i++) bias1[i] = b1[o1 + i];
#pragma unroll
    for (int i = 0; i < 8; i++) bias2[i] = b2[o2 + i];

    __syncthreads();

    for (int g = blockIdx.x; g < B_BAT * NPOINT; g += gridDim.x) {
        const int b = g >> 10;
        const int s = g & 1023;
        const float* px = xyz + (size_t)b * 3 * NPTS;
        const float* pp = pts + (size_t)b * DIN * NPTS;

        if (t < NSAMP) nbr[t] = g_nb[g * NSAMP + t];
        if (t == NSAMP) {
            int qi = g_fps[g];
            qp[0] = px[qi]; qp[1] = px[NPTS + qi]; qp[2] = px[2 * NPTS + qi];
        }
        __syncthreads();

        // gather X0[k][c]
        for (int j = t; j < NSAMP * CIN0; j += 512) {
            int c = j >> 5, k = j & 31;
            int nk = nbr[k];
            float v = (c < 3) ? (px[c * NPTS + nk] - qp[c])
                              : pp[(c - 3) * NPTS + nk];
            X0[k * 68 + c] = v;
        }
        __syncthreads();

        // ---- Layer 0: 67 -> 64, tile 1k x 4o (f32x2) ----
        {
            unsigned long long a0 = 0, a1 = 0;
            const float* xr = &X0[kt0 * 68];
            const float* wb = &W0t[o0];
#pragma unroll 4
            for (int c = 0; c < CIN0; c++) {
                ulonglong2 w = *(const ulonglong2*)(wb + c * 64);
                unsigned long long xx; PACK2(xx, xr[c]);
                FMA2(a0, xx, w.x);
                FMA2(a1, xx, w.y);
            }
            float v0, v1, v2, v3;
            UNPACK2(v0, v1, a0);
            UNPACK2(v2, v3, a1);
            float4 h = make_float4(silu_f(v0 + bias0[0]), silu_f(v1 + bias0[1]),
                                   silu_f(v2 + bias0[2]), silu_f(v3 + bias0[3]));
            *(float4*)&H1[kt0 * 64 + o0] = h;
        }
        __syncthreads();

        // ---- Layer 1: 64 -> 128, tile 1k x 8o (f32x2) ----
        {
            unsigned long long a0 = 0, a1 = 0, a2 = 0, a3 = 0;
            const float* xr = &H1[kt1 * 64];
            const float* wb = &W1t[o1];
#pragma unroll 4
            for (int c = 0; c < H1DIM; c++) {
                ulonglong2 wA = *(const ulonglong2*)(wb + c * 128);
                ulonglong2 wB = *(const ulonglong2*)(wb + c * 128 + 4);
                unsigned long long xx; PACK2(xx, xr[c]);
                FMA2(a0, xx, wA.x); FMA2(a1, xx, wA.y);
                FMA2(a2, xx, wB.x); FMA2(a3, xx, wB.y);
            }
            float v[8];
            UNPACK2(v[0], v[1], a0); UNPACK2(v[2], v[3], a1);
            UNPACK2(v[4], v[5], a2); UNPACK2(v[6], v[7], a3);
            float4 hA = make_float4(silu_f(v[0] + bias1[0]), silu_f(v[1] + bias1[1]),
                                    silu_f(v[2] + bias1[2]), silu_f(v[3] + bias1[3]));
            float4 hB = make_float4(silu_f(v[4] + bias1[4]), silu_f(v[5] + bias1[5]),
                                    silu_f(v[6] + bias1[6]), silu_f(v[7] + bias1[7]));
            *(float4*)&H2[kt1 * 128 + o1]     = hA;
            *(float4*)&H2[kt1 * 128 + o1 + 4] = hB;
        }
        __syncthreads();

        // ---- Layer 2: 128 -> 256, tile 2k x 8o (f32x2), fused silu + k-sum ----
        {
            unsigned long long a0 = 0, a1 = 0, a2 = 0, a3 = 0;
            unsigned long long c0 = 0, c1 = 0, c2 = 0, c3 = 0;
            const float* xr0 = &H2[k2 * 128];
            const float* xr1 = xr0 + 128;
            const float* wb  = &W2t[o2];
#pragma unroll 2
            for (int c = 0; c < H2DIM; c++) {
                ulonglong2 wA = *(const ulonglong2*)(wb + c * 256);
                ulonglong2 wB = *(const ulonglong2*)(wb + c * 256 + 4);
                unsigned long long x0, x1;
                PACK2(x0, xr0[c]); PACK2(x1, xr1[c]);
                FMA2(a0, x0, wA.x); FMA2(a1, x0, wA.y);
                FMA2(a2, x0, wB.x); FMA2(a3, x0, wB.y);
                FMA2(c0, x1, wA.x); FMA2(c1, x1, wA.y);
                FMA2(c2, x1, wB.x); FMA2(c3, x1, wB.y);
            }
            float u[8], w[8];
            UNPACK2(u[0], u[1], a0); UNPACK2(u[2], u[3], a1);
            UNPACK2(u[4], u[5], a2); UNPACK2(u[6], u[7], a3);
            UNPACK2(w[0], w[1], c0); UNPACK2(w[2], w[3], c1);
            UNPACK2(w[4], w[5], c2); UNPACK2(w[6], w[7], c3);
            float part[8];
#pragma unroll
            for (int j = 0; j < 8; j++)
                part[j] = silu_f(u[j] + bias2[j]) + silu_f(w[j] + bias2[j]);
            *(float4*)&Red[kt2 * 256 + o2]     = make_float4(part[0], part[1], part[2], part[3]);
            *(float4*)&Red[kt2 * 256 + o2 + 4] = make_float4(part[4], part[5], part[6], part[7]);
        }
        __syncthreads();

        // mean over 32 samples: sum the 16 partial rows, one o per thread
        if (t < H3DIM) {
            float sum = 0.0f;
#pragma unroll
            for (int r = 0; r < 16; r++) sum += Red[r * 256 + t];
            out[(size_t)b * (H3DIM * NPOINT) + (size_t)t * NPOINT + s] = sum * (1.0f / 32.0f);
        }
        __syncthreads();
    }
}

// ---------------------------------------------------------------------------
extern "C" void kernel_launch(void* const* d_in, const int* in_sizes, int n_in,
                              void* d_out, int out_size) {
    const float* xyz = (const float*)d_in[0];
    const float* pts = (const float*)d_in[1];
    const float* w0  = (const float*)d_in[2];
    const float* b0  = (const float*)d_in[3];
    const float* w1  = (const float*)d_in[4];
    const float* b1  = (const float*)d_in[5];
    const float* w2  = (const float*)d_in[6];
    const float* b2  = (const float*)d_in[7];
    float* out = (float*)d_out;

    const int mlp_smem = MLP_SMEM_FLOATS * (int)sizeof(float);   // 214416 B
    cudaFuncSetAttribute(mlp_kernel, cudaFuncAttributeMaxDynamicSharedMemorySize, mlp_smem);

    prep_kernel<<<(45248 + 255) / 256, 256>>>(w0, w1, w2);
    fps_kernel<<<B_BAT * 8, 256>>>(xyz);
    bq_kernel<<<(B_BAT * NPOINT) / 8, 256>>>(xyz);
    mlp_kernel<<<148, 512, mlp_smem>>>(xyz, pts, b0, b1, b2, out);
}

// round 8
// speedup vs baseline: 1.3926x; 1.3358x over previous
#include <cuda_runtime.h>
#include <cuda_bf16.h>

#define NPTS   16384
#define B_BAT  8
#define NPOINT 1024
#define NSAMP  32
#define DIN    64
#define CIN0   67
#define H1DIM  64
#define H2DIM  128
#define H3DIM  256

// Scratch (device globals; no runtime allocation)
__device__ int   g_fps[B_BAT * NPOINT];
__device__ int   g_nb[B_BAT * NPOINT * NSAMP];
__device__ float g_Wt[4288 + 8192 + 32768];   // W0t(67x64) | W1t(64x128) | W2t(128x256)

// exact (non-contracted) squared distance, XLA reduce order ((dx^2+dy^2)+dz^2)
__device__ __forceinline__ float sqdist(float dx, float dy, float dz) {
    return __fadd_rn(__fadd_rn(__fmul_rn(dx, dx), __fmul_rn(dy, dy)), __fmul_rn(dz, dz));
}

__device__ __forceinline__ float silu_f(float x) {
    return __fdividef(x, 1.0f + __expf(-x));
}

// ---- packed fp32x2 helpers (sm_103a FFMA2 path) ----
#define FMA2(acc, x, w) asm("fma.rn.f32x2 %0, %1, %2, %0;" : "+l"(acc) : "l"(x), "l"(w))
#define PACK2(d, s)     asm("mov.b64 %0, {%1, %1};" : "=l"(d) : "f"(s))
#define UNPACK2(lo, hi, v) asm("mov.b64 {%0, %1}, %2;" : "=f"(lo), "=f"(hi) : "l"(v))

// ---------------------------------------------------------------------------
// Kernel 1: farthest point sampling, 8-CTA cluster per batch. (unchanged)
// ---------------------------------------------------------------------------
__global__ void __launch_bounds__(256, 1) __cluster_dims__(8, 1, 1)
fps_kernel(const float* __restrict__ xyz) {
    __shared__ float slots[2][8][8];
    __shared__ float s_wv[8];
    __shared__ int   s_wi[8];

    unsigned rank;
    asm("mov.u32 %0, %%cluster_ctarank;" : "=r"(rank));
    const int b = blockIdx.x >> 3;
    const int t = threadIdx.x;
    const float* px = xyz + (size_t)b * 3 * NPTS;
    const int base = (int)rank * 2048;

    unsigned slot_base;
    asm("{ .reg .u64 tt; cvta.to.shared.u64 tt, %1; cvt.u32.u64 %0, tt; }"
        : "=r"(slot_base) : "l"(&slots[0][0][0]));

    float x[8], y[8], z[8], dist[8];
#pragma unroll
    for (int j = 0; j < 8; j++) {
        int p = base + j * 256 + t;
        x[j] = px[p];
        y[j] = px[NPTS + p];
        z[j] = px[2 * NPTS + p];
        dist[j] = __int_as_float(0x7f800000);
    }
    float cx = px[0], cy = px[NPTS], cz = px[2 * NPTS];
    int cur = 0;

    for (int s = 0; s < NPOINT; s++) {
        if (rank == 0 && t == 0) g_fps[b * NPOINT + s] = cur;

        float bv = -1.0f;
        int   bi = 0;
#pragma unroll
        for (int j = 0; j < 8; j++) {
            float dx = __fsub_rn(x[j], cx);
            float dy = __fsub_rn(y[j], cy);
            float dz = __fsub_rn(z[j], cz);
            float d  = sqdist(dx, dy, dz);
            float nd = fminf(dist[j], d);
            dist[j] = nd;
            if (nd > bv) { bv = nd; bi = base + j * 256 + t; }
        }
        unsigned vb = __float_as_uint(bv);
        unsigned mv = __reduce_max_sync(0xffffffffu, vb);
        unsigned ic = (vb == mv) ? (unsigned)bi : 0xffffffffu;
        unsigned mi = __reduce_min_sync(0xffffffffu, ic);
        if ((t & 31) == 0) { s_wv[t >> 5] = __uint_as_float(mv); s_wi[t >> 5] = (int)mi; }
        __syncthreads();

        float cv = s_wv[0]; int cp = s_wi[0];
#pragma unroll
        for (int r = 1; r < 8; r++) {
            float fv = s_wv[r]; int fi = s_wi[r];
            if (fv > cv || (fv == cv && fi < cp)) { cv = fv; cp = fi; }
        }

        int local = cp - base;
        if ((local & 255) == t) {
            int j = local >> 8;
            float ox = x[0], oy = y[0], oz = z[0];
#pragma unroll
            for (int jj = 1; jj < 8; jj++)
                if (jj == j) { ox = x[jj]; oy = y[jj]; oz = z[jj]; }
            unsigned la = slot_base + (unsigned)(((s & 1) * 8 + (int)rank) * 8) * 4u;
#pragma unroll
            for (int r = 0; r < 8; r++) {
                unsigned ra;
                asm("mapa.shared::cluster.u32 %0, %1, %2;" : "=r"(ra) : "r"(la), "r"(r));
                asm volatile("st.shared::cluster.f32 [%0], %1;"    :: "r"(ra), "f"(cv));
                asm volatile("st.shared::cluster.u32 [%0+4], %1;"  :: "r"(ra), "r"((unsigned)cp));
                asm volatile("st.shared::cluster.f32 [%0+8], %1;"  :: "r"(ra), "f"(ox));
                asm volatile("st.shared::cluster.f32 [%0+12], %1;" :: "r"(ra), "f"(oy));
                asm volatile("st.shared::cluster.f32 [%0+16], %1;" :: "r"(ra), "f"(oz));
            }
        }
        asm volatile("barrier.cluster.arrive.aligned;" ::: "memory");
        asm volatile("barrier.cluster.wait.aligned;"   ::: "memory");

        const float* rec = &slots[s & 1][0][0];
        float gv = rec[0];
        int   gp = (int)__float_as_uint(rec[1]);
        float nx = rec[2], ny = rec[3], nz = rec[4];
#pragma unroll
        for (int r = 1; r < 8; r++) {
            const float* rr = rec + r * 8;
            float fv = rr[0];
            int   fi = (int)__float_as_uint(rr[1]);
            if (fv > gv || (fv == gv && fi < gp)) {
                gv = fv; gp = fi; nx = rr[2]; ny = rr[3]; nz = rr[4];
            }
        }
        cur = gp; cx = nx; cy = ny; cz = nz;
    }
}

// ---------------------------------------------------------------------------
// Kernel 2: ball query. (unchanged)
// ---------------------------------------------------------------------------
__global__ void bq_kernel(const float* __restrict__ xyz) {
    const int warp = (blockIdx.x * blockDim.x + threadIdx.x) >> 5;
    const int lane = threadIdx.x & 31;
    if (warp >= B_BAT * NPOINT) return;
    const int b = warp >> 10;

    const float* px = xyz + (size_t)b * 3 * NPTS;
    const int qi = g_fps[warp];
    const float qx = px[qi], qy = px[NPTS + qi], qz = px[2 * NPTS + qi];

    int cnt = 0;
    int first = 0;
    for (int ch = 0; ch < NPTS / 32; ch++) {
        if (cnt >= NSAMP) break;
        int p = ch * 32 + lane;
        float dx = __fsub_rn(px[p], qx);
        float dy = __fsub_rn(px[NPTS + p], qy);
        float dz = __fsub_rn(px[2 * NPTS + p], qz);
        float d  = sqdist(dx, dy, dz);
        bool ok = !(d > 0.04f);
        unsigned mask = __ballot_sync(0xffffffffu, ok);
        if (cnt == 0 && mask) first = ch * 32 + (__ffs(mask) - 1);
        int rank = cnt + __popc(mask & ((1u << lane) - 1u));
        if (ok && rank < NSAMP) g_nb[warp * NSAMP + rank] = p;
        cnt += __popc(mask);
    }
    if (cnt < NSAMP) {
        for (int r = cnt + lane; r < NSAMP; r += 32)
            g_nb[warp * NSAMP + r] = first;
    }
}

// ---------------------------------------------------------------------------
// Kernel 3: transpose weights into g_Wt as Wt[c][o]. (unchanged)
// ---------------------------------------------------------------------------
__global__ void prep_kernel(const float* __restrict__ w0,
                            const float* __restrict__ w1,
                            const float* __restrict__ w2) {
    int i = blockIdx.x * 256 + threadIdx.x;
    if (i < 4288) {
        int c = i >> 6, o = i & 63;
        g_Wt[i] = w0[o * CIN0 + c];
    } else if (i < 4288 + 8192) {
        int j = i - 4288;
        int c = j >> 7, o = j & 127;
        g_Wt[i] = w1[o * H1DIM + c];
    } else if (i < 4288 + 8192 + 32768) {
        int j = i - (4288 + 8192);
        int c = j >> 8, o = j & 255;
        g_Wt[i] = w2[o * H2DIM + c];
    }
}

// ---------------------------------------------------------------------------
// Kernel 4: fused gather + MLP + mean. 512 threads, persistent, 2 groups/iter,
// TRANSPOSED activations [c][k] so x loads are warp-broadcast vector LDS.
// smem (floats):
//   W0t 0 | W1t 4288 | W2t 12480 |
//   AB  45248 : X0t(67x64=4288) then reused by H2t(128x64=8192) -> 45248..53440
//   H1t 53440 (64x64=4096), aliased by Red(16x256=4096)
//   nbr 57536 (64 int) | q 57600 (6) -> total 57606 floats (230424 B)
// ---------------------------------------------------------------------------
#define SM_W0   0
#define SM_W1   4288
#define SM_W2   12480
#define SM_X0   45248
#define SM_H2   45248
#define SM_H1   53440
#define SM_RED  53440
#define SM_NBR  57536
#define SM_Q    57600
#define MLP_SMEM_FLOATS 57608

__global__ void __launch_bounds__(512, 1)
mlp_kernel(const float* __restrict__ xyz, const float* __restrict__ pts,
           const float* __restrict__ b0, const float* __restrict__ b1,
           const float* __restrict__ b2, float* __restrict__ out) {
    extern __shared__ float smf[];
    float* W0t = smf + SM_W0;
    float* W1t = smf + SM_W1;
    float* W2t = smf + SM_W2;
    float* X0t = smf + SM_X0;   // [67][64]
    float* H2t = smf + SM_H2;   // [128][64] (reuses X0t region)
    float* H1t = smf + SM_H1;   // [64][64]
    float* Red = smf + SM_RED;  // [16][256] (reuses H1t region)
    int*   nbr = (int*)(smf + SM_NBR);
    float* qp  = smf + SM_Q;

    const int t = threadIdx.x;

    // stage weights once per CTA
    {
        const float4* src = (const float4*)g_Wt;
        float4* dst = (float4*)smf;
        for (int i = t; i < 45248 / 4; i += 512) dst[i] = src[i];
    }

    // tile coordinates
    const int ot0 = t & 15, kt0 = t >> 4;           // L0: 2k x 4o
    const int o0 = ot0 * 4,  k0a = kt0 * 2;
    const int ot1 = t & 15, kt1 = t >> 4;           // L1: 2k x 8o
    const int o1 = ot1 * 8,  k1a = kt1 * 2;
    const int ot2 = t & 31, kt2 = t >> 5;           // L2: 4k x 8o
    const int o2 = ot2 * 8,  k2a = kt2 * 4;

    float bias0[4], bias1[8], bias2[8];
#pragma unroll
    for (int i = 0; i < 4; i++) bias0[i] = b0[o0 + i];
#pragma unroll
    for (int i = 0; i < 8; i++) bias1[i] = b1[o1 + i];
#pragma unroll
    for (int i = 0; i < 8; i++) bias2[i] = b2[o2 + i];

    __syncthreads();

    // 2 groups per iteration
    for (int pg = blockIdx.x; pg < (B_BAT * NPOINT) / 2; pg += gridDim.x) {
        const int g0 = pg * 2;

        if (t < 64) {
            int gi = t >> 5;
            nbr[t] = g_nb[(g0 + gi) * NSAMP + (t & 31)];
        }
        if (t >= 64 && t < 66) {
            int gi = t - 64;
            int g = g0 + gi;
            int b = g >> 10;
            const float* px = xyz + (size_t)b * 3 * NPTS;
            int qi = g_fps[g];
            qp[gi * 3 + 0] = px[qi];
            qp[gi * 3 + 1] = px[NPTS + qi];
            qp[gi * 3 + 2] = px[2 * NPTS + qi];
        }
        __syncthreads();

        // gather X0t[c][k], k in [0,64): group = k>>5
        {
            const int b0i = g0 >> 10;            // both groups same batch? not nec.
            const int b1i = (g0 + 1) >> 10;
            const float* px0 = xyz + (size_t)b0i * 3 * NPTS;
            const float* pp0 = pts + (size_t)b0i * DIN * NPTS;
            const float* px1 = xyz + (size_t)b1i * 3 * NPTS;
            const float* pp1 = pts + (size_t)b1i * DIN * NPTS;
            for (int j = t; j < 64 * CIN0; j += 512) {
                int c = j >> 6, k = j & 63;
                int gi = k >> 5;
                int nk = nbr[k];
                const float* px = gi ? px1 : px0;
                const float* pp = gi ? pp1 : pp0;
                float v = (c < 3) ? (px[c * NPTS + nk] - qp[gi * 3 + c])
                                  : pp[(c - 3) * NPTS + nk];
                X0t[c * 64 + k] = v;
            }
        }
        __syncthreads();

        // ---- Layer 0: 67 -> 64, tile 2k x 4o ----
        {
            unsigned long long a00 = 0, a01 = 0, a10 = 0, a11 = 0;
#pragma unroll 4
            for (int c = 0; c < CIN0; c++) {
                float2 xv = *(const float2*)&X0t[c * 64 + k0a];
                ulonglong2 w = *(const ulonglong2*)&W0t[c * 64 + o0];
                unsigned long long x0, x1;
                PACK2(x0, xv.x); PACK2(x1, xv.y);
                FMA2(a00, x0, w.x); FMA2(a01, x0, w.y);
                FMA2(a10, x1, w.x); FMA2(a11, x1, w.y);
            }
            float v[2][4];
            UNPACK2(v[0][0], v[0][1], a00); UNPACK2(v[0][2], v[0][3], a01);
            UNPACK2(v[1][0], v[1][1], a10); UNPACK2(v[1][2], v[1][3], a11);
            __syncthreads();   // X0t region about to stay, H1t write ok (distinct)
#pragma unroll
            for (int j = 0; j < 4; j++) {
                float2 hv = make_float2(silu_f(v[0][j] + bias0[j]),
                                        silu_f(v[1][j] + bias0[j]));
                *(float2*)&H1t[(o0 + j) * 64 + k0a] = hv;
            }
        }
        __syncthreads();

        // ---- Layer 1: 64 -> 128, tile 2k x 8o (writes H2t over X0t) ----
        {
            unsigned long long a0[4] = {0,0,0,0}, a1[4] = {0,0,0,0};
#pragma unroll 4
            for (int c = 0; c < H1DIM; c++) {
                float2 xv = *(const float2*)&H1t[c * 64 + k1a];
                ulonglong2 wA = *(const ulonglong2*)&W1t[c * 128 + o1];
                ulonglong2 wB = *(const ulonglong2*)&W1t[c * 128 + o1 + 4];
                unsigned long long x0, x1;
                PACK2(x0, xv.x); PACK2(x1, xv.y);
                FMA2(a0[0], x0, wA.x); FMA2(a0[1], x0, wA.y);
                FMA2(a0[2], x0, wB.x); FMA2(a0[3], x0, wB.y);
                FMA2(a1[0], x1, wA.x); FMA2(a1[1], x1, wA.y);
                FMA2(a1[2], x1, wB.x); FMA2(a1[3], x1, wB.y);
            }
            float v0[8], v1[8];
            UNPACK2(v0[0], v0[1], a0[0]); UNPACK2(v0[2], v0[3], a0[1]);
            UNPACK2(v0[4], v0[5], a0[2]); UNPACK2(v0[6], v0[7], a0[3]);
            UNPACK2(v1[0], v1[1], a1[0]); UNPACK2(v1[2], v1[3], a1[1]);
            UNPACK2(v1[4], v1[5], a1[2]); UNPACK2(v1[6], v1[7], a1[3]);
#pragma unroll
            for (int j = 0; j < 8; j++) {
                float2 hv = make_float2(silu_f(v0[j] + bias1[j]),
                                        silu_f(v1[j] + bias1[j]));
                *(float2*)&H2t[(o1 + j) * 64 + k1a] = hv;
            }
        }
        __syncthreads();

        // ---- Layer 2: 128 -> 256, tile 4k x 8o, fused silu + k-partial-sum ----
        {
            unsigned long long a[4][4];
#pragma unroll
            for (int kk = 0; kk < 4; kk++)
#pragma unroll
                for (int j = 0; j < 4; j++) a[kk][j] = 0;
#pragma unroll 4
            for (int c = 0; c < H2DIM; c++) {
                float4 xv = *(const float4*)&H2t[c * 64 + k2a];
                ulonglong2 wA = *(const ulonglong2*)&W2t[c * 256 + o2];
                ulonglong2 wB = *(const ulonglong2*)&W2t[c * 256 + o2 + 4];
                unsigned long long x0, x1, x2, x3;
                PACK2(x0, xv.x); PACK2(x1, xv.y); PACK2(x2, xv.z); PACK2(x3, xv.w);
                FMA2(a[0][0], x0, wA.x); FMA2(a[0][1], x0, wA.y);
                FMA2(a[0][2], x0, wB.x); FMA2(a[0][3], x0, wB.y);
                FMA2(a[1][0], x1, wA.x); FMA2(a[1][1], x1, wA.y);
                FMA2(a[1][2], x1, wB.x); FMA2(a[1][3], x1, wB.y);
                FMA2(a[2][0], x2, wA.x); FMA2(a[2][1], x2, wA.y);
                FMA2(a[2][2], x2, wB.x); FMA2(a[2][3], x2, wB.y);
                FMA2(a[3][0], x3, wA.x); FMA2(a[3][1], x3, wA.y);
                FMA2(a[3][2], x3, wB.x); FMA2(a[3][3], x3, wB.y);
            }
            float u[4][8];
#pragma unroll
            for (int kk = 0; kk < 4; kk++) {
                UNPACK2(u[kk][0], u[kk][1], a[kk][0]);
                UNPACK2(u[kk][2], u[kk][3], a[kk][1]);
                UNPACK2(u[kk][4], u[kk][5], a[kk][2]);
                UNPACK2(u[kk][6], u[kk][7], a[kk][3]);
            }
            float part[8];
#pragma unroll
            for (int j = 0; j < 8; j++) {
                float bb = bias2[j];
                float sum = silu_f(u[0][j] + bb);
                sum += silu_f(u[1][j] + bb);
                sum += silu_f(u[2][j] + bb);
                sum += silu_f(u[3][j] + bb);
                part[j] = sum;
            }
            __syncthreads();   // H1t fully consumed; Red (alias) safe to write
            *(float4*)&Red[kt2 * 256 + o2]     = make_float4(part[0], part[1], part[2], part[3]);
            *(float4*)&Red[kt2 * 256 + o2 + 4] = make_float4(part[4], part[5], part[6], part[7]);
        }
        __syncthreads();

        // mean over 32 samples: gi = t>>8 selects group, o = t&255
        {
            int gi = t >> 8;
            int o  = t & 255;
            float sum = 0.0f;
#pragma unroll
            for (int r = 0; r < 8; r++) sum += Red[(gi * 8 + r) * 256 + o];
            int g = g0 + gi;
            int b = g >> 10;
            int s = g & 1023;
            out[(size_t)b * (H3DIM * NPOINT) + (size_t)o * NPOINT + s] = sum * (1.0f / 32.0f);
        }
        __syncthreads();
    }
}

// ---------------------------------------------------------------------------
extern "C" void kernel_launch(void* const* d_in, const int* in_sizes, int n_in,
                              void* d_out, int out_size) {
    const float* xyz = (const float*)d_in[0];
    const float* pts = (const float*)d_in[1];
    const float* w0  = (const float*)d_in[2];
    const float* b0  = (const float*)d_in[3];
    const float* w1  = (const float*)d_in[4];
    const float* b1  = (const float*)d_in[5];
    const float* w2  = (const float*)d_in[6];
    const float* b2  = (const float*)d_in[7];
    float* out = (float*)d_out;

    const int mlp_smem = MLP_SMEM_FLOATS * (int)sizeof(float);   // 230432 B
    cudaFuncSetAttribute(mlp_kernel, cudaFuncAttributeMaxDynamicSharedMemorySize, mlp_smem);

    prep_kernel<<<(45248 + 255) / 256, 256>>>(w0, w1, w2);
    fps_kernel<<<B_BAT * 8, 256>>>(xyz);
    bq_kernel<<<(B_BAT * NPOINT) / 8, 256>>>(xyz);
    mlp_kernel<<<148, 512, mlp_smem>>>(xyz, pts, b0, b1, b2, out);
}

// round 9
// speedup vs baseline: 1.6505x; 1.1852x over previous
#include <cuda_runtime.h>
#include <cuda_bf16.h>

#define NPTS   16384
#define B_BAT  8
#define NPOINT 1024
#define NSAMP  32
#define DIN    64
#define CIN0   67
#define H1DIM  64
#define H2DIM  128
#define H3DIM  256

// Scratch (device globals; no runtime allocation)
__device__ int   g_fps[B_BAT * NPOINT];
__device__ int   g_nb[B_BAT * NPOINT * NSAMP];
__device__ float g_Wt[4288 + 8192 + 32768];   // W0t(67x64) | W1t(64x128) | W2t(128x256)

// exact (non-contracted) squared distance, XLA reduce order ((dx^2+dy^2)+dz^2)
__device__ __forceinline__ float sqdist(float dx, float dy, float dz) {
    return __fadd_rn(__fadd_rn(__fmul_rn(dx, dx), __fmul_rn(dy, dy)), __fmul_rn(dz, dz));
}

__device__ __forceinline__ float silu_f(float x) {
    return __fdividef(x, 1.0f + __expf(-x));
}

// ---- packed fp32x2 helpers (sm_103a FFMA2 path) ----
#define FMA2(acc, x, w) asm("fma.rn.f32x2 %0, %1, %2, %0;" : "+l"(acc) : "l"(x), "l"(w))
#define PACK2(d, s)     asm("mov.b64 %0, {%1, %1};" : "=l"(d) : "f"(s))
#define UNPACK2(lo, hi, v) asm("mov.b64 {%0, %1}, %2;" : "=f"(lo), "=f"(hi) : "l"(v))

// XOR-4 swizzle on the k index, keyed by row c. Multiple of 4 => preserves
// float2/float4 alignment and intra-block order. Makes L0/L1 activation
// STORES conflict-free while reads stay warp-broadcast.
#define SWZ(c, k) ((k) ^ ((((c) >> 2) & 7) << 2))

// ---------------------------------------------------------------------------
// Kernel 1: farthest point sampling, 8-CTA cluster per batch. (unchanged)
// ---------------------------------------------------------------------------
__global__ void __launch_bounds__(256, 1) __cluster_dims__(8, 1, 1)
fps_kernel(const float* __restrict__ xyz) {
    __shared__ float slots[2][8][8];
    __shared__ float s_wv[8];
    __shared__ int   s_wi[8];

    unsigned rank;
    asm("mov.u32 %0, %%cluster_ctarank;" : "=r"(rank));
    const int b = blockIdx.x >> 3;
    const int t = threadIdx.x;
    const float* px = xyz + (size_t)b * 3 * NPTS;
    const int base = (int)rank * 2048;

    unsigned slot_base;
    asm("{ .reg .u64 tt; cvta.to.shared.u64 tt, %1; cvt.u32.u64 %0, tt; }"
        : "=r"(slot_base) : "l"(&slots[0][0][0]));

    float x[8], y[8], z[8], dist[8];
#pragma unroll
    for (int j = 0; j < 8; j++) {
        int p = base + j * 256 + t;
        x[j] = px[p];
        y[j] = px[NPTS + p];
        z[j] = px[2 * NPTS + p];
        dist[j] = __int_as_float(0x7f800000);
    }
    float cx = px[0], cy = px[NPTS], cz = px[2 * NPTS];
    int cur = 0;

    for (int s = 0; s < NPOINT; s++) {
        if (rank == 0 && t == 0) g_fps[b * NPOINT + s] = cur;

        float bv = -1.0f;
        int   bi = 0;
#pragma unroll
        for (int j = 0; j < 8; j++) {
            float dx = __fsub_rn(x[j], cx);
            float dy = __fsub_rn(y[j], cy);
            float dz = __fsub_rn(z[j], cz);
            float d  = sqdist(dx, dy, dz);
            float nd = fminf(dist[j], d);
            dist[j] = nd;
            if (nd > bv) { bv = nd; bi = base + j * 256 + t; }
        }
        unsigned vb = __float_as_uint(bv);
        unsigned mv = __reduce_max_sync(0xffffffffu, vb);
        unsigned ic = (vb == mv) ? (unsigned)bi : 0xffffffffu;
        unsigned mi = __reduce_min_sync(0xffffffffu, ic);
        if ((t & 31) == 0) { s_wv[t >> 5] = __uint_as_float(mv); s_wi[t >> 5] = (int)mi; }
        __syncthreads();

        float cv = s_wv[0]; int cp = s_wi[0];
#pragma unroll
        for (int r = 1; r < 8; r++) {
            float fv = s_wv[r]; int fi = s_wi[r];
            if (fv > cv || (fv == cv && fi < cp)) { cv = fv; cp = fi; }
        }

        int local = cp - base;
        if ((local & 255) == t) {
            int j = local >> 8;
            float ox = x[0], oy = y[0], oz = z[0];
#pragma unroll
            for (int jj = 1; jj < 8; jj++)
                if (jj == j) { ox = x[jj]; oy = y[jj]; oz = z[jj]; }
            unsigned la = slot_base + (unsigned)(((s & 1) * 8 + (int)rank) * 8) * 4u;
#pragma unroll
            for (int r = 0; r < 8; r++) {
                unsigned ra;
                asm("mapa.shared::cluster.u32 %0, %1, %2;" : "=r"(ra) : "r"(la), "r"(r));
                asm volatile("st.shared::cluster.f32 [%0], %1;"    :: "r"(ra), "f"(cv));
                asm volatile("st.shared::cluster.u32 [%0+4], %1;"  :: "r"(ra), "r"((unsigned)cp));
                asm volatile("st.shared::cluster.f32 [%0+8], %1;"  :: "r"(ra), "f"(ox));
                asm volatile("st.shared::cluster.f32 [%0+12], %1;" :: "r"(ra), "f"(oy));
                asm volatile("st.shared::cluster.f32 [%0+16], %1;" :: "r"(ra), "f"(oz));
            }
        }
        asm volatile("barrier.cluster.arrive.aligned;" ::: "memory");
        asm volatile("barrier.cluster.wait.aligned;"   ::: "memory");

        const float* rec = &slots[s & 1][0][0];
        float gv = rec[0];
        int   gp = (int)__float_as_uint(rec[1]);
        float nx = rec[2], ny = rec[3], nz = rec[4];
#pragma unroll
        for (int r = 1; r < 8; r++) {
            const float* rr = rec + r * 8;
            float fv = rr[0];
            int   fi = (int)__float_as_uint(rr[1]);
            if (fv > gv || (fv == gv && fi < gp)) {
                gv = fv; gp = fi; nx = rr[2]; ny = rr[3]; nz = rr[4];
            }
        }
        cur = gp; cx = nx; cy = ny; cz = nz;
    }
}

// ---------------------------------------------------------------------------
// Kernel 2: ball query. (unchanged)
// ---------------------------------------------------------------------------
__global__ void bq_kernel(const float* __restrict__ xyz) {
    const int warp = (blockIdx.x * blockDim.x + threadIdx.x) >> 5;
    const int lane = threadIdx.x & 31;
    if (warp >= B_BAT * NPOINT) return;
    const int b = warp >> 10;

    const float* px = xyz + (size_t)b * 3 * NPTS;
    const int qi = g_fps[warp];
    const float qx = px[qi], qy = px[NPTS + qi], qz = px[2 * NPTS + qi];

    int cnt = 0;
    int first = 0;
    for (int ch = 0; ch < NPTS / 32; ch++) {
        if (cnt >= NSAMP) break;
        int p = ch * 32 + lane;
        float dx = __fsub_rn(px[p], qx);
        float dy = __fsub_rn(px[NPTS + p], qy);
        float dz = __fsub_rn(px[2 * NPTS + p], qz);
        float d  = sqdist(dx, dy, dz);
        bool ok = !(d > 0.04f);
        unsigned mask = __ballot_sync(0xffffffffu, ok);
        if (cnt == 0 && mask) first = ch * 32 + (__ffs(mask) - 1);
        int rank = cnt + __popc(mask & ((1u << lane) - 1u));
        if (ok && rank < NSAMP) g_nb[warp * NSAMP + rank] = p;
        cnt += __popc(mask);
    }
    if (cnt < NSAMP) {
        for (int r = cnt + lane; r < NSAMP; r += 32)
            g_nb[warp * NSAMP + r] = first;
    }
}

// ---------------------------------------------------------------------------
// Kernel 3: transpose weights into g_Wt as Wt[c][o]. (unchanged)
// ---------------------------------------------------------------------------
__global__ void prep_kernel(const float* __restrict__ w0,
                            const float* __restrict__ w1,
                            const float* __restrict__ w2) {
    int i = blockIdx.x * 256 + threadIdx.x;
    if (i < 4288) {
        int c = i >> 6, o = i & 63;
        g_Wt[i] = w0[o * CIN0 + c];
    } else if (i < 4288 + 8192) {
        int j = i - 4288;
        int c = j >> 7, o = j & 127;
        g_Wt[i] = w1[o * H1DIM + c];
    } else if (i < 4288 + 8192 + 32768) {
        int j = i - (4288 + 8192);
        int c = j >> 8, o = j & 255;
        g_Wt[i] = w2[o * H2DIM + c];
    }
}

// ---------------------------------------------------------------------------
// Kernel 4: fused gather + MLP + mean. 512 threads, persistent, 2 groups/iter.
// Conflict-free tiles: L0 2k x 4o, L1 4k x 4o, L2 8k x 4o; weight LDS.128 at
// 16B lane stride; activation reads warp-broadcast; H1t/H2t XOR-swizzled so
// producer stores are also conflict-free.
// smem (floats):
//   W0t 0 | W1t 4288 | W2t 12480 |
//   H2t 45248 [128][64]=8192 (overlays X0t [67][64]=4288)
//   H1t 53440 [64][64]=4096  (overlaid by Red [8][256]=2048)
//   nbr 57536 (64 int) | q 57600 (6) -> total 57608 floats (230432 B)
// ---------------------------------------------------------------------------
#define SM_W0   0
#define SM_W1   4288
#define SM_W2   12480
#define SM_X0   45248
#define SM_H2   45248
#define SM_H1   53440
#define SM_RED  53440
#define SM_NBR  57536
#define SM_Q    57600
#define MLP_SMEM_FLOATS 57608

__global__ void __launch_bounds__(512, 1)
mlp_kernel(const float* __restrict__ xyz, const float* __restrict__ pts,
           const float* __restrict__ b0, const float* __restrict__ b1,
           const float* __restrict__ b2, float* __restrict__ out) {
    extern __shared__ float smf[];
    float* W0t = smf + SM_W0;
    float* W1t = smf + SM_W1;
    float* W2t = smf + SM_W2;
    float* X0t = smf + SM_X0;   // [67][64]
    float* H2t = smf + SM_H2;   // [128][64], k swizzled
    float* H1t = smf + SM_H1;   // [64][64], k swizzled
    float* Red = smf + SM_RED;  // [8][256]
    int*   nbr = (int*)(smf + SM_NBR);
    float* qp  = smf + SM_Q;

    const int t = threadIdx.x;

    // stage weights once per CTA
    {
        const float4* src = (const float4*)g_Wt;
        float4* dst = (float4*)smf;
        for (int i = t; i < 45248 / 4; i += 512) dst[i] = src[i];
    }

    // tile coordinates
    const int o0 = (t & 15) * 4, k0a = (t >> 4) * 2;   // L0: 2k x 4o
    const int o1 = (t & 31) * 4, k1  = (t >> 5) * 4;   // L1: 4k x 4o
    const int o2 = (t & 63) * 4, kt2 = (t >> 6);       // L2: 8k x 4o
    const int k2 = kt2 * 8;

    float bias0[4], bias1[4], bias2[4];
#pragma unroll
    for (int i = 0; i < 4; i++) bias0[i] = b0[o0 + i];
#pragma unroll
    for (int i = 0; i < 4; i++) bias1[i] = b1[o1 + i];
#pragma unroll
    for (int i = 0; i < 4; i++) bias2[i] = b2[o2 + i];

    __syncthreads();

    // 2 groups (64 sample-rows) per iteration
    for (int pg = blockIdx.x; pg < (B_BAT * NPOINT) / 2; pg += gridDim.x) {
        const int g0 = pg * 2;

        if (t < 64) {
            int gi = t >> 5;
            nbr[t] = g_nb[(g0 + gi) * NSAMP + (t & 31)];
        }
        if (t >= 64 && t < 66) {
            int gi = t - 64;
            int g = g0 + gi;
            int b = g >> 10;
            const float* px = xyz + (size_t)b * 3 * NPTS;
            int qi = g_fps[g];
            qp[gi * 3 + 0] = px[qi];
            qp[gi * 3 + 1] = px[NPTS + qi];
            qp[gi * 3 + 2] = px[2 * NPTS + qi];
        }
        __syncthreads();

        // gather X0t[c][k]
        {
            const int b0i = g0 >> 10;
            const int b1i = (g0 + 1) >> 10;
            const float* px0 = xyz + (size_t)b0i * 3 * NPTS;
            const float* pp0 = pts + (size_t)b0i * DIN * NPTS;
            const float* px1 = xyz + (size_t)b1i * 3 * NPTS;
            const float* pp1 = pts + (size_t)b1i * DIN * NPTS;
            for (int j = t; j < 64 * CIN0; j += 512) {
                int c = j >> 6, k = j & 63;
                int gi = k >> 5;
                int nk = nbr[k];
                const float* px = gi ? px1 : px0;
                const float* pp = gi ? pp1 : pp0;
                float v = (c < 3) ? (px[c * NPTS + nk] - qp[gi * 3 + c])
                                  : pp[(c - 3) * NPTS + nk];
                X0t[c * 64 + k] = v;
            }
        }
        __syncthreads();

        // ---- Layer 0: 67 -> 64, tile 2k x 4o ----
        {
            unsigned long long a00 = 0, a01 = 0, a10 = 0, a11 = 0;
#pragma unroll 4
            for (int c = 0; c < CIN0; c++) {
                float2 xv = *(const float2*)&X0t[c * 64 + k0a];
                ulonglong2 w = *(const ulonglong2*)&W0t[c * 64 + o0];
                unsigned long long x0, x1;
                PACK2(x0, xv.x); PACK2(x1, xv.y);
                FMA2(a00, x0, w.x); FMA2(a01, x0, w.y);
                FMA2(a10, x1, w.x); FMA2(a11, x1, w.y);
            }
            float v[2][4];
            UNPACK2(v[0][0], v[0][1], a00); UNPACK2(v[0][2], v[0][3], a01);
            UNPACK2(v[1][0], v[1][1], a10); UNPACK2(v[1][2], v[1][3], a11);
#pragma unroll
            for (int j = 0; j < 4; j++) {
                int c = o0 + j;
                float2 hv = make_float2(silu_f(v[0][j] + bias0[j]),
                                        silu_f(v[1][j] + bias0[j]));
                *(float2*)&H1t[c * 64 + SWZ(c, k0a)] = hv;
            }
        }
        __syncthreads();

        // ---- Layer 1: 64 -> 128, tile 4k x 4o (writes H2t over X0t) ----
        {
            unsigned long long a[4][2];
#pragma unroll
            for (int kk = 0; kk < 4; kk++) { a[kk][0] = 0; a[kk][1] = 0; }
#pragma unroll 4
            for (int c = 0; c < H1DIM; c++) {
                float4 xv = *(const float4*)&H1t[c * 64 + SWZ(c, k1)];
                ulonglong2 w = *(const ulonglong2*)&W1t[c * 128 + o1];
                unsigned long long x0, x1, x2, x3;
                PACK2(x0, xv.x); PACK2(x1, xv.y); PACK2(x2, xv.z); PACK2(x3, xv.w);
                FMA2(a[0][0], x0, w.x); FMA2(a[0][1], x0, w.y);
                FMA2(a[1][0], x1, w.x); FMA2(a[1][1], x1, w.y);
                FMA2(a[2][0], x2, w.x); FMA2(a[2][1], x2, w.y);
                FMA2(a[3][0], x3, w.x); FMA2(a[3][1], x3, w.y);
            }
            float v[4][4];
#pragma unroll
            for (int kk = 0; kk < 4; kk++) {
                UNPACK2(v[kk][0], v[kk][1], a[kk][0]);
                UNPACK2(v[kk][2], v[kk][3], a[kk][1]);
            }
#pragma unroll
            for (int j = 0; j < 4; j++) {
                int c = o1 + j;
                float4 hv = make_float4(silu_f(v[0][j] + bias1[j]),
                                        silu_f(v[1][j] + bias1[j]),
                                        silu_f(v[2][j] + bias1[j]),
                                        silu_f(v[3][j] + bias1[j]));
                *(float4*)&H2t[c * 64 + SWZ(c, k1)] = hv;
            }
        }
        __syncthreads();

        // ---- Layer 2: 128 -> 256, tile 8k x 4o, fused silu + k-partial-sum ----
        {
            unsigned long long a[8][2];
#pragma unroll
            for (int kk = 0; kk < 8; kk++) { a[kk][0] = 0; a[kk][1] = 0; }
#pragma unroll 2
            for (int c = 0; c < H2DIM; c++) {
                float4 xa = *(const float4*)&H2t[c * 64 + SWZ(c, k2)];
                float4 xb = *(const float4*)&H2t[c * 64 + SWZ(c, k2 + 4)];
                ulonglong2 w = *(const ulonglong2*)&W2t[c * 256 + o2];
                unsigned long long x0, x1, x2, x3;
                PACK2(x0, xa.x); PACK2(x1, xa.y); PACK2(x2, xa.z); PACK2(x3, xa.w);
                FMA2(a[0][0], x0, w.x); FMA2(a[0][1], x0, w.y);
                FMA2(a[1][0], x1, w.x); FMA2(a[1][1], x1, w.y);
                FMA2(a[2][0], x2, w.x); FMA2(a[2][1], x2, w.y);
                FMA2(a[3][0], x3, w.x); FMA2(a[3][1], x3, w.y);
                PACK2(x0, xb.x); PACK2(x1, xb.y); PACK2(x2, xb.z); PACK2(x3, xb.w);
                FMA2(a[4][0], x0, w.x); FMA2(a[4][1], x0, w.y);
                FMA2(a[5][0], x1, w.x); FMA2(a[5][1], x1, w.y);
                FMA2(a[6][0], x2, w.x); FMA2(a[6][1], x2, w.y);
                FMA2(a[7][0], x3, w.x); FMA2(a[7][1], x3, w.y);
            }
            float u[8][4];
#pragma unroll
            for (int kk = 0; kk < 8; kk++) {
                UNPACK2(u[kk][0], u[kk][1], a[kk][0]);
                UNPACK2(u[kk][2], u[kk][3], a[kk][1]);
            }
            float part[4];
#pragma unroll
            for (int j = 0; j < 4; j++) {
                float bb = bias2[j];
                float sum = silu_f(u[0][j] + bb);
#pragma unroll
                for (int kk = 1; kk < 8; kk++) sum += silu_f(u[kk][j] + bb);
                part[j] = sum;
            }
            __syncthreads();   // H1t reads done; Red (alias) safe to write
            *(float4*)&Red[kt2 * 256 + o2] = make_float4(part[0], part[1], part[2], part[3]);
        }
        __syncthreads();

        // mean over 32 samples: gi = t>>8 selects group, o = t&255
        {
            int gi = t >> 8;
            int o  = t & 255;
            float sum = 0.0f;
#pragma unroll
            for (int r = 0; r < 4; r++) sum += Red[(gi * 4 + r) * 256 + o];
            int g = g0 + gi;
            int b = g >> 10;
            int s = g & 1023;
            out[(size_t)b * (H3DIM * NPOINT) + (size_t)o * NPOINT + s] = sum * (1.0f / 32.0f);
        }
        __syncthreads();
    }
}

// ---------------------------------------------------------------------------
extern "C" void kernel_launch(void* const* d_in, const int* in_sizes, int n_in,
                              void* d_out, int out_size) {
    const float* xyz = (const float*)d_in[0];
    const float* pts = (const float*)d_in[1];
    const float* w0  = (const float*)d_in[2];
    const float* b0  = (const float*)d_in[3];
    const float* w1  = (const float*)d_in[4];
    const float* b1  = (const float*)d_in[5];
    const float* w2  = (const float*)d_in[6];
    const float* b2  = (const float*)d_in[7];
    float* out = (float*)d_out;

    const int mlp_smem = MLP_SMEM_FLOATS * (int)sizeof(float);   // 230432 B
    cudaFuncSetAttribute(mlp_kernel, cudaFuncAttributeMaxDynamicSharedMemorySize, mlp_smem);

    prep_kernel<<<(45248 + 255) / 256, 256>>>(w0, w1, w2);
    fps_kernel<<<B_BAT * 8, 256>>>(xyz);
    bq_kernel<<<(B_BAT * NPOINT) / 8, 256>>>(xyz);
    mlp_kernel<<<148, 512, mlp_smem>>>(xyz, pts, b0, b1, b2, out);
}